// round 4
// baseline (speedup 1.0000x reference)
#include <cuda_runtime.h>
#include <cstdint>
#include <cstddef>

#define NB   32
#define NFR  16
#define NT   192
#define DD   256
#define NS   21
#define BSROWS (NB*NS)          // 672
#define SM_SCALE 0.0625f        // D^-0.5
#define ATT_EPS 1e-8f
#define LN_EPS  1e-5f

// ---------------- scratch (device globals; no allocation) ----------------
static __device__ float g_k[(size_t)NB*NFR*NT*DD];   // [B,NF,N,D]
static __device__ float g_v[(size_t)NB*NFR*NT*DD];
static __device__ float g_slots[BSROWS*DD];
static __device__ float g_q[BSROWS*DD];
static __device__ float g_upd[BSROWS*DD];
static __device__ float g_gi[BSROWS*3*DD];
static __device__ float g_gh[BSROWS*3*DD];
static __device__ float g_h[BSROWS*DD];
static __device__ float g_t[BSROWS*DD];

// ---------------- generic tiled SGEMM: C = [epi](LN?(A) @ W^T + bias) ----
// A: [M,256], W: [N,256] row-major, C: [M,N]. BN=64, BK=32, K=256 fixed.
// EPI: 0 none, 1 relu, 2 +R (residual, R stride 256)
template<int BM, bool LN, int EPI>
__global__ void sgemm_nt(const float* __restrict__ A,
                         const float* __restrict__ W,
                         const float* __restrict__ bias,
                         float* __restrict__ C,
                         int M, int N,
                         const float* __restrict__ gamma,
                         const float* __restrict__ beta,
                         const float* __restrict__ R)
{
    constexpr int BK = 32;
    constexpr int NTH = BM * 4;
    constexpr int PADA = BM + 4;
    __shared__ float As[BK][PADA];
    __shared__ float Ws[BK][68];
    __shared__ float s_mean[BM], s_rstd[BM];
    __shared__ float s_red[BM][4][2];

    const int tid  = threadIdx.x;
    const int row0 = blockIdx.y * BM;
    const int col0 = blockIdx.x * 64;

    if (LN) {
        int r = tid >> 2, p = tid & 3;
        float s = 0.f, s2 = 0.f;
        if (row0 + r < M) {
            const float4* ap = reinterpret_cast<const float4*>(A + (size_t)(row0 + r) * DD + p * 64);
            #pragma unroll
            for (int u = 0; u < 16; ++u) {
                float4 x = ap[u];
                s  += x.x + x.y + x.z + x.w;
                s2 += x.x*x.x + x.y*x.y + x.z*x.z + x.w*x.w;
            }
        }
        s_red[r][p][0] = s; s_red[r][p][1] = s2;
        __syncthreads();
        if (tid < BM) {
            float ss  = s_red[tid][0][0]+s_red[tid][1][0]+s_red[tid][2][0]+s_red[tid][3][0];
            float ss2 = s_red[tid][0][1]+s_red[tid][1][1]+s_red[tid][2][1]+s_red[tid][3][1];
            float m = ss * (1.0f/DD);
            s_mean[tid] = m;
            s_rstd[tid] = rsqrtf(ss2*(1.0f/DD) - m*m + LN_EPS);
        }
        __syncthreads();
    }

    float acc[4][4] = {};
    const int ty = tid >> 4;
    const int tx = tid & 15;

    for (int kk = 0; kk < DD; kk += BK) {
        #pragma unroll
        for (int l = 0; l < 2; ++l) {                 // A tile (transposed)
            int t = tid + l * NTH;
            int i = t >> 3;
            int kq = (t & 7) << 2;
            float4 v = make_float4(0.f,0.f,0.f,0.f);
            if (row0 + i < M)
                v = *reinterpret_cast<const float4*>(A + (size_t)(row0 + i) * DD + kk + kq);
            if (LN) {
                float m = s_mean[i], rs = s_rstd[i];
                float4 g  = *reinterpret_cast<const float4*>(gamma + kk + kq);
                float4 bb = *reinterpret_cast<const float4*>(beta  + kk + kq);
                v.x = (v.x - m)*rs*g.x + bb.x;
                v.y = (v.y - m)*rs*g.y + bb.y;
                v.z = (v.z - m)*rs*g.z + bb.z;
                v.w = (v.w - m)*rs*g.w + bb.w;
            }
            As[kq+0][i]=v.x; As[kq+1][i]=v.y; As[kq+2][i]=v.z; As[kq+3][i]=v.w;
        }
        #pragma unroll
        for (int l = 0; l < 512/NTH; ++l) {           // W tile (transposed)
            int t = tid + l * NTH;
            int j = t >> 3;
            int kq = (t & 7) << 2;
            float4 v = *reinterpret_cast<const float4*>(W + (size_t)(col0 + j) * DD + kk + kq);
            Ws[kq+0][j]=v.x; Ws[kq+1][j]=v.y; Ws[kq+2][j]=v.z; Ws[kq+3][j]=v.w;
        }
        __syncthreads();
        #pragma unroll
        for (int k = 0; k < BK; ++k) {
            float4 a = *reinterpret_cast<const float4*>(&As[k][ty<<2]);
            float4 b = *reinterpret_cast<const float4*>(&Ws[k][tx<<2]);
            acc[0][0]+=a.x*b.x; acc[0][1]+=a.x*b.y; acc[0][2]+=a.x*b.z; acc[0][3]+=a.x*b.w;
            acc[1][0]+=a.y*b.x; acc[1][1]+=a.y*b.y; acc[1][2]+=a.y*b.z; acc[1][3]+=a.y*b.w;
            acc[2][0]+=a.z*b.x; acc[2][1]+=a.z*b.y; acc[2][2]+=a.z*b.z; acc[2][3]+=a.z*b.w;
            acc[3][0]+=a.w*b.x; acc[3][1]+=a.w*b.y; acc[3][2]+=a.w*b.z; acc[3][3]+=a.w*b.w;
        }
        __syncthreads();
    }

    float4 bb = *reinterpret_cast<const float4*>(bias + col0 + (tx<<2));
    #pragma unroll
    for (int ii = 0; ii < 4; ++ii) {
        int r = row0 + (ty<<2) + ii;
        if (r < M) {
            float4 o;
            o.x = acc[ii][0] + bb.x;
            o.y = acc[ii][1] + bb.y;
            o.z = acc[ii][2] + bb.z;
            o.w = acc[ii][3] + bb.w;
            if (EPI == 1) {
                o.x = fmaxf(o.x, 0.f); o.y = fmaxf(o.y, 0.f);
                o.z = fmaxf(o.z, 0.f); o.w = fmaxf(o.w, 0.f);
            }
            if (EPI == 2) {
                float4 rr = *reinterpret_cast<const float4*>(R + (size_t)r * DD + col0 + (tx<<2));
                o.x += rr.x; o.y += rr.y; o.z += rr.z; o.w += rr.w;
            }
            *reinterpret_cast<float4*>(C + (size_t)r * N + col0 + (tx<<2)) = o;
        }
    }
}

// ---------------- attention: dots + column softmax (+eps) -> out_attn ----
// grid (3, B), 128 threads. Columns j0..j0+63 of frame f; softmax over 21 slots.
__global__ void attn_kernel(const float* __restrict__ q,
                            const float* __restrict__ kall,
                            float* __restrict__ out_attn, int f)
{
    constexpr int BK = 32;
    __shared__ float As[BK][36];
    __shared__ float Ws[BK][68];
    __shared__ float dt[NS][64];

    int b  = blockIdx.y;
    int j0 = blockIdx.x * 64;
    const float* Ab = q + (size_t)b * NS * DD;
    const float* Wb = kall + ((size_t)(b*NFR + f) * NT + j0) * DD;
    int tid = threadIdx.x;
    int ty = tid >> 4, tx = tid & 15;
    float acc[4][4] = {};

    for (int kk = 0; kk < DD; kk += BK) {
        #pragma unroll
        for (int l = 0; l < 2; ++l) {
            int t = tid + l * 128;
            int i = t >> 3, kq = (t & 7) << 2;
            float4 v = make_float4(0.f,0.f,0.f,0.f);
            if (i < NS) v = *reinterpret_cast<const float4*>(Ab + (size_t)i * DD + kk + kq);
            As[kq+0][i]=v.x; As[kq+1][i]=v.y; As[kq+2][i]=v.z; As[kq+3][i]=v.w;
        }
        #pragma unroll
        for (int l = 0; l < 4; ++l) {
            int t = tid + l * 128;
            int j = t >> 3, kq = (t & 7) << 2;
            float4 v = *reinterpret_cast<const float4*>(Wb + (size_t)j * DD + kk + kq);
            Ws[kq+0][j]=v.x; Ws[kq+1][j]=v.y; Ws[kq+2][j]=v.z; Ws[kq+3][j]=v.w;
        }
        __syncthreads();
        #pragma unroll
        for (int k = 0; k < BK; ++k) {
            float4 a = *reinterpret_cast<const float4*>(&As[k][ty<<2]);
            float4 b4 = *reinterpret_cast<const float4*>(&Ws[k][tx<<2]);
            acc[0][0]+=a.x*b4.x; acc[0][1]+=a.x*b4.y; acc[0][2]+=a.x*b4.z; acc[0][3]+=a.x*b4.w;
            acc[1][0]+=a.y*b4.x; acc[1][1]+=a.y*b4.y; acc[1][2]+=a.y*b4.z; acc[1][3]+=a.y*b4.w;
            acc[2][0]+=a.z*b4.x; acc[2][1]+=a.z*b4.y; acc[2][2]+=a.z*b4.z; acc[2][3]+=a.z*b4.w;
            acc[3][0]+=a.w*b4.x; acc[3][1]+=a.w*b4.y; acc[3][2]+=a.w*b4.z; acc[3][3]+=a.w*b4.w;
        }
        __syncthreads();
    }
    #pragma unroll
    for (int ii = 0; ii < 4; ++ii) {
        int i = (ty<<2) + ii;
        if (i < NS) {
            dt[i][(tx<<2)+0] = acc[ii][0]*SM_SCALE;
            dt[i][(tx<<2)+1] = acc[ii][1]*SM_SCALE;
            dt[i][(tx<<2)+2] = acc[ii][2]*SM_SCALE;
            dt[i][(tx<<2)+3] = acc[ii][3]*SM_SCALE;
        }
    }
    __syncthreads();
    if (tid < 64) {
        int j = tid;
        float m = -1e30f;
        #pragma unroll
        for (int i = 0; i < NS; ++i) m = fmaxf(m, dt[i][j]);
        float e[NS];
        float s = 0.f;
        #pragma unroll
        for (int i = 0; i < NS; ++i) { e[i] = __expf(dt[i][j] - m); s += e[i]; }
        float inv = 1.0f / s;
        float* op = out_attn + ((size_t)(b*NFR + f) * NS) * NT + j0 + j;
        #pragma unroll
        for (int i = 0; i < NS; ++i) op[(size_t)i * NT] = e[i]*inv + ATT_EPS;
    }
}

// ---------------- updates = (attn_ori @ v) / rowsum(attn_ori) ------------
// grid (4, B), 256 threads. d-tile of 64; j split over 4 thread groups.
__global__ void upd_kernel(const float* __restrict__ attn,
                           const float* __restrict__ vall,
                           float* __restrict__ upd, int f)
{
    __shared__ float a_s[NS*NT];
    __shared__ float rsum[NS];
    __shared__ float red[4][NS][64];

    int b  = blockIdx.y;
    int d0 = blockIdx.x * 64;
    int tid = threadIdx.x;
    const float* ab = attn + (size_t)(b*NFR + f) * NS * NT;
    for (int t = tid; t < NS*NT; t += 256) a_s[t] = ab[t];
    __syncthreads();
    if (tid < NS) {
        float s = 0.f;
        const float* row = &a_s[tid * NT];
        for (int j = 0; j < NT; ++j) s += row[j];
        rsum[tid] = 1.0f / s;
    }
    int jg = tid >> 6, dl = tid & 63;
    const float* vb = vall + ((size_t)(b*NFR + f) * NT) * DD + d0 + dl;
    float acc[NS] = {};
    int jbase = jg * 48;
    for (int j4 = 0; j4 < 48; j4 += 4) {
        float v0 = vb[(size_t)(jbase + j4 + 0) * DD];
        float v1 = vb[(size_t)(jbase + j4 + 1) * DD];
        float v2 = vb[(size_t)(jbase + j4 + 2) * DD];
        float v3 = vb[(size_t)(jbase + j4 + 3) * DD];
        #pragma unroll
        for (int i = 0; i < NS; ++i) {
            float4 a = *reinterpret_cast<const float4*>(&a_s[i*NT + jbase + j4]);
            acc[i] += a.x*v0 + a.y*v1 + a.z*v2 + a.w*v3;
        }
    }
    #pragma unroll
    for (int i = 0; i < NS; ++i) red[jg][i][dl] = acc[i];
    __syncthreads();
    if (tid < 64) {
        #pragma unroll
        for (int i = 0; i < NS; ++i) {
            float s = red[0][i][tid] + red[1][i][tid] + red[2][i][tid] + red[3][i][tid];
            upd[((size_t)b*NS + i) * DD + d0 + tid] = s * rsum[i];
        }
    }
}

// ---------------- GRU gates ----------------------------------------------
__global__ void gru_gate(const float* __restrict__ gi,
                         const float* __restrict__ gh,
                         const float* __restrict__ slots,
                         float* __restrict__ h)
{
    int row = blockIdx.x;
    int c = threadIdx.x;
    size_t base = (size_t)row * 3 * DD;
    float ir = gi[base + c],        hr = gh[base + c];
    float iz = gi[base + DD + c],   hz = gh[base + DD + c];
    float in = gi[base + 2*DD + c], hn = gh[base + 2*DD + c];
    float r = 1.0f / (1.0f + __expf(-(ir + hr)));
    float z = 1.0f / (1.0f + __expf(-(iz + hz)));
    float n = tanhf(in + r * hn);
    float hh = slots[(size_t)row * DD + c];
    h[(size_t)row * DD + c] = (1.0f - z) * n + z * hh;
}

// ---------------- misc ----------------------------------------------------
__global__ void init_slots(const float* __restrict__ noise,
                           const float* __restrict__ mu,
                           const float* __restrict__ sg,
                           float* __restrict__ slots)
{
    int idx = blockIdx.x * 256 + threadIdx.x;
    int d = idx & (DD - 1);
    slots[idx] = mu[d] + sg[d] * noise[idx];
}

__global__ void copy_slots_out(const float* __restrict__ slots, float* __restrict__ out)
{
    int idx = blockIdx.x * 256 + threadIdx.x;   // 32*20*256
    int d = idx & (DD - 1);
    int srow = idx >> 8;                         // b*20 + s
    int b = srow / 20, s = srow - b * 20;
    out[idx] = slots[((size_t)b * NS + s) * DD + d];
}

// ---------------- launch ---------------------------------------------------
extern "C" void kernel_launch(void* const* d_in, const int* in_sizes, int n_in,
                              void* d_out, int out_size)
{
    const float* inputs = (const float*)d_in[0];
    const float* noise  = (const float*)d_in[1];
    const float* mu     = (const float*)d_in[2];
    const float* sigma  = (const float*)d_in[3];
    const float* Wq = (const float*)d_in[4];   const float* bq = (const float*)d_in[5];
    const float* Wk = (const float*)d_in[6];   const float* bk = (const float*)d_in[7];
    const float* Wv = (const float*)d_in[8];   const float* bv = (const float*)d_in[9];
    const float* W1 = (const float*)d_in[10];  const float* b1 = (const float*)d_in[11];
    const float* W2 = (const float*)d_in[12];  const float* b2 = (const float*)d_in[13];
    const float* W_ih = (const float*)d_in[14]; const float* b_ih = (const float*)d_in[15];
    const float* W_hh = (const float*)d_in[16]; const float* b_hh = (const float*)d_in[17];
    const float* g_in = (const float*)d_in[18]; const float* be_in = (const float*)d_in[19];
    const float* g_sl = (const float*)d_in[20]; const float* be_sl = (const float*)d_in[21];
    const float* g_ff = (const float*)d_in[22]; const float* be_ff = (const float*)d_in[23];

    float* out = (float*)d_out;
    float* out_slots = out;
    float* out_attn  = out + NB * 20 * DD;

    float *pk, *pv, *pslots, *pq, *pupd, *pgi, *pgh, *ph, *pt;
    cudaGetSymbolAddress((void**)&pk, g_k);
    cudaGetSymbolAddress((void**)&pv, g_v);
    cudaGetSymbolAddress((void**)&pslots, g_slots);
    cudaGetSymbolAddress((void**)&pq, g_q);
    cudaGetSymbolAddress((void**)&pupd, g_upd);
    cudaGetSymbolAddress((void**)&pgi, g_gi);
    cudaGetSymbolAddress((void**)&pgh, g_gh);
    cudaGetSymbolAddress((void**)&ph, g_h);
    cudaGetSymbolAddress((void**)&pt, g_t);

    // slots0 = mu + sigma * noise
    init_slots<<<BSROWS, 256>>>(noise, mu, sigma, pslots);

    // k,v projections for all frames (LN fused)
    {
        const int M = NB * NFR * NT;          // 98304
        dim3 grid(DD / 64, M / 64);           // (4, 1536)
        sgemm_nt<64, true, 0><<<grid, 256>>>(inputs, Wk, bk, pk, M, DD, g_in, be_in, nullptr);
        sgemm_nt<64, true, 0><<<grid, 256>>>(inputs, Wv, bv, pv, M, DD, g_in, be_in, nullptr);
    }

    for (int f = 0; f < NFR; ++f) {
        for (int t = 0; t < 3; ++t) {
            // q = LN(slots) @ Wq^T + bq
            sgemm_nt<32, true, 0><<<dim3(4, 21), 128>>>(pslots, Wq, bq, pq, BSROWS, DD, g_sl, be_sl, nullptr);
            // dots + softmax(+eps) -> out_attn (last iter's write persists)
            attn_kernel<<<dim3(3, NB), 128>>>(pq, pk, out_attn, f);
            // updates
            upd_kernel<<<dim3(4, NB), 256>>>(out_attn, pv, pupd, f);
            // GRU gate projections
            sgemm_nt<32, false, 0><<<dim3(12, 21), 128>>>(pupd,   W_ih, b_ih, pgi, BSROWS, 3*DD, nullptr, nullptr, nullptr);
            sgemm_nt<32, false, 0><<<dim3(12, 21), 128>>>(pslots, W_hh, b_hh, pgh, BSROWS, 3*DD, nullptr, nullptr, nullptr);
            gru_gate<<<BSROWS, 256>>>(pgi, pgh, pslots, ph);
            // MLP: slots = h + relu(LN(h) @ W1^T + b1) @ W2^T + b2
            sgemm_nt<32, true, 1><<<dim3(4, 21), 128>>>(ph, W1, b1, pt, BSROWS, DD, g_ff, be_ff, nullptr);
            sgemm_nt<32, false, 2><<<dim3(4, 21), 128>>>(pt, W2, b2, pslots, BSROWS, DD, nullptr, nullptr, ph);
        }
    }

    copy_slots_out<<<(NB * 20 * DD) / 256, 256>>>(pslots, out_slots);
}